// round 8
// baseline (speedup 1.0000x reference)
#include <cuda_runtime.h>
#include <cstdint>

// ---------------------------------------------------------------------------
// Sequential LSTM rollout, N=10000 steps, H=1024.
// 128 persistent CTAs x 256 threads, W_hh in registers (f32x2 pairs).
// Publish: lanes<8 st.cg h -> __syncwarp -> lane0 red.release.gpu.add
//          group_counter[cta>>4], 1   (release orders the h stores; no fence)
// Observe: warp w's lane0 polls ld.acquire.gpu counter[w] >= 16*t — group w
//          (CTAs 16w..16w+15) are EXACTLY the producers of warp w's k-slice
//          h[128w,128w+128). No smem relay; each warp starts as soon as its
//          slice is complete. Counters 128B-spaced (one line each).
// Run-ahead bounded to 1 step: a CTA publishes t+1 only after all 8 of its
// warps' polls (covering ALL 128 CTAs) passed 16*(t+1) -> parity
// double-buffered g_hbuf / sh_part safe with ONE __syncthreads per step.
// CTA b owns h[8b..8b+8) and gate rows {g*1024 + 8b + j}.
// Warp w owns k in [128w,128w+128).
// ---------------------------------------------------------------------------

#define HDIM  1024
#define NCTA  128
#define TPB   256
#define NWARP 8
#define WPT   64           // f32x2 weight pairs per thread (=128 k floats)
#define CSTRIDE 32         // counters spaced 32 uints = 128 B

typedef unsigned long long ull;

__device__ __align__(16)  float    g_hbuf[2][HDIM];
__device__ __align__(128) unsigned g_cnt[NWARP * CSTRIDE];

__device__ __forceinline__ ull ffma2(ull a, ull b, ull c) {
    ull d;
    asm("fma.rn.f32x2 %0, %1, %2, %3;" : "=l"(d) : "l"(a), "l"(b), "l"(c));
    return d;
}
__device__ __forceinline__ ull fadd2(ull a, ull b) {
    ull d;
    asm("add.rn.f32x2 %0, %1, %2;" : "=l"(d) : "l"(a), "l"(b));
    return d;
}
__device__ __forceinline__ float pairsum(ull a) {
    float lo = __uint_as_float((unsigned)(a & 0xffffffffull));
    float hi = __uint_as_float((unsigned)(a >> 32));
    return lo + hi;
}
__device__ __forceinline__ float sigf(float x) {
    return 1.0f / (1.0f + __expf(-x));
}
__device__ __forceinline__ unsigned ld_acq_gpu(const unsigned* p) {
    unsigned v;
    asm volatile("ld.acquire.gpu.u32 %0, [%1];" : "=r"(v) : "l"(p));
    return v;
}

__global__ void lstm_init_kernel() {
    int i = threadIdx.x;
    if (i < NWARP) g_cnt[i * CSTRIDE] = 0u;
}

__global__ void __launch_bounds__(TPB) lstm_kernel(
    const float* __restrict__ x,      // [1024]
    const float* __restrict__ W_ih,   // [4096,1024] row-major
    const float* __restrict__ W_hh,   // [4096,1024] row-major
    const float* __restrict__ b_ih,   // [4096]
    const float* __restrict__ b_hh,   // [4096]
    float* __restrict__ out,          // [N,1024]
    int N)
{
    __shared__ float sh_h[HDIM];           // warp w owns [128w,128w+128): private
    __shared__ float sh_part[2][TPB];      // parity-double-buffered partials

    const int tid = threadIdx.x;
    const int w   = tid >> 5;
    const int l   = tid & 31;
    const int cta = blockIdx.x;
    const int gt  = l >> 3;                // gate 0..3 (i,f,g,o)
    const int jj  = l & 7;                 // local h index 0..7
    const int rowG = gt * HDIM + cta * 8 + jj;

    const unsigned* myCnt  = &g_cnt[w * CSTRIDE];          // poll target (warp slice)
    unsigned*       pubCnt = &g_cnt[(cta >> 4) * CSTRIDE]; // publish target (own group)

    // ---- stage x into shared (reuse sh_h) ----
    ((float4*)sh_h)[tid] = ((const float4*)x)[tid];
    __syncthreads();

    // ---- prologue: x_gates = x @ W_ih^T + b_ih + b_hh for this CTA's rows ----
    float xg = 0.f;
    {
        const ull* wp = (const ull*)W_ih + (size_t)rowG * (HDIM / 2) + w * WPT;
        const ull* hp = (const ull*)sh_h + w * WPT;
        ull a0 = 0, a1 = 0, a2 = 0, a3 = 0;
        #pragma unroll
        for (int i = 0; i < WPT; i += 4) {
            a0 = ffma2(wp[i + 0], hp[i + 0], a0);
            a1 = ffma2(wp[i + 1], hp[i + 1], a1);
            a2 = ffma2(wp[i + 2], hp[i + 2], a2);
            a3 = ffma2(wp[i + 3], hp[i + 3], a3);
        }
        a0 = fadd2(a0, a1); a2 = fadd2(a2, a3); a0 = fadd2(a0, a2);
        sh_part[0][w * 32 + l] = pairsum(a0);
        __syncthreads();
        if (w == 0) {
            float s = 0.f;
            #pragma unroll
            for (int ww = 0; ww < NWARP; ww++) s += sh_part[0][ww * 32 + l];
            xg = s + b_ih[rowG] + b_hh[rowG];
        }
        __syncthreads();
    }

    // ---- preload W_hh slice into registers ----
    ull wreg[WPT];
    {
        const ull* wp = (const ull*)W_hh + (size_t)rowG * (HDIM / 2) + w * WPT;
        #pragma unroll
        for (int i = 0; i < WPT; i++) wreg[i] = wp[i];
    }

    // ---- recurrence: ONE __syncthreads per step ----
    float c = 0.f;
    unsigned target = 0u;                  // = 16*t

    for (int t = 0; t < N; ++t) {
        float dot = 0.f;
        if (t > 0) {
            const int p = (t - 1) & 1;

            // warp-local poll: group w counter covers exactly this warp's slice
            if (l == 0) {
                while ((int)(ld_acq_gpu(myCnt) - target) < 0) { }
            }
            __syncwarp();

            // stage this warp's k-slice into its private smem region
            float4 hv = __ldcg((const float4*)(g_hbuf[p] + w * 128) + l);
            *((float4*)(sh_h + w * 128) + l) = hv;
            __syncwarp();

            const ull* hp = (const ull*)(sh_h + w * 128);
            ull c0 = 0, c1 = 0, c2 = 0, c3 = 0;
            #pragma unroll
            for (int i = 0; i < WPT; i += 4) {
                c0 = ffma2(wreg[i + 0], hp[i + 0], c0);
                c1 = ffma2(wreg[i + 1], hp[i + 1], c1);
                c2 = ffma2(wreg[i + 2], hp[i + 2], c2);
                c3 = ffma2(wreg[i + 3], hp[i + 3], c3);
            }
            c0 = fadd2(c0, c1); c2 = fadd2(c2, c3); c0 = fadd2(c0, c2);
            dot = pairsum(c0);
        }
        sh_part[t & 1][w * 32 + l] = dot;
        __syncthreads();

        if (w == 0) {
            float s = 0.f;
            #pragma unroll
            for (int ww = 0; ww < NWARP; ww++) s += sh_part[t & 1][ww * 32 + l];
            // activation on ALL 32 lanes (parallel MUFU), then gather
            float val = xg + s;
            float act = (gt == 2) ? tanhf(val) : sigf(val);
            float a_f = __shfl_sync(0xffffffffu, act, l + 8);
            float a_g = __shfl_sync(0xffffffffu, act, l + 16);
            float a_o = __shfl_sync(0xffffffffu, act, l + 24);
            float hn = 0.f;
            if (l < 8) {
                c  = a_f * c + act * a_g;       // act=i, a_f=f, a_g=g
                hn = a_o * tanhf(c);
                __stcg(&g_hbuf[t & 1][cta * 8 + l], hn);
            }
            __syncwarp();
            if (l == 0) {
                // release increment: orders the h stores, no separate fence
                asm volatile("red.release.gpu.global.add.u32 [%0], %1;"
                             :: "l"(pubCnt), "r"(1u) : "memory");
            }
            // out store AFTER release: never delays the publish
            if (l < 8)
                __stcs(out + (size_t)t * HDIM + cta * 8 + l, hn);
        }
        target += 16u;
        // no trailing barrier: sh_part for step t+1 has opposite parity; group
        // counters transitively bound cross-CTA skew to 1 step (see header).
    }
}

extern "C" void kernel_launch(void* const* d_in, const int* in_sizes, int n_in,
                              void* d_out, int out_size) {
    const float* x    = (const float*)d_in[0];
    const float* W_ih = (const float*)d_in[1];
    const float* W_hh = (const float*)d_in[2];
    const float* b_ih = (const float*)d_in[3];
    const float* b_hh = (const float*)d_in[4];
    float* out = (float*)d_out;
    const int N = out_size / HDIM;

    lstm_init_kernel<<<1, 32>>>();
    lstm_kernel<<<NCTA, TPB>>>(x, W_ih, W_hh, b_ih, b_hh, out, N);
}

// round 9
// speedup vs baseline: 1.8129x; 1.8129x over previous
#include <cuda_runtime.h>
#include <cstdint>

// ---------------------------------------------------------------------------
// Sequential LSTM rollout, N=10000 steps, H=1024.
// 128 persistent CTAs x 512 threads, W_hh in registers (f32x2 pairs).
// Protocol = R7 (proven fastest): single aggregate counter g_cnt;
//   Publish: lanes<8 of warp0 st.cg h -> __syncwarp -> lane0 __threadfence ->
//            red.global.add g_cnt,1
//   Observe: lane0 polls ld.acquire.gpu g_cnt >= 128*t, relays via smem
//            (st.release.cta / ld.acquire.cta spin). One __syncthreads/step.
// R9 changes: library tanhf -> expf-based fast tanh (both call sites);
//             512 threads (16 warps x 64-float slices) halves matvec latency.
// CTA b owns h[8b..8b+8) and gate rows {g*1024 + 8b + j}.
// Warp w owns k in [64w,64w+64).
// ---------------------------------------------------------------------------

#define HDIM  1024
#define NCTA  128
#define TPB   512
#define NWARP 16
#define WPT   32           // f32x2 weight pairs per thread (=64 k floats)

typedef unsigned long long ull;

__device__ __align__(16) float g_hbuf[2][HDIM];
__device__ unsigned            g_cnt;

__device__ __forceinline__ ull ffma2(ull a, ull b, ull c) {
    ull d;
    asm("fma.rn.f32x2 %0, %1, %2, %3;" : "=l"(d) : "l"(a), "l"(b), "l"(c));
    return d;
}
__device__ __forceinline__ ull fadd2(ull a, ull b) {
    ull d;
    asm("add.rn.f32x2 %0, %1, %2;" : "=l"(d) : "l"(a), "l"(b));
    return d;
}
__device__ __forceinline__ float pairsum(ull a) {
    float lo = __uint_as_float((unsigned)(a & 0xffffffffull));
    float hi = __uint_as_float((unsigned)(a >> 32));
    return lo + hi;
}
__device__ __forceinline__ float sigf(float x) {
    return 1.0f / (1.0f + __expf(-x));
}
// fast, accurate tanh: (1-e)/(1+e), e = exp(-2x); clamp avoids inf/inf NaN
__device__ __forceinline__ float tanh_fast(float x) {
    x = fminf(15.0f, fmaxf(-15.0f, x));
    float e = __expf(-2.0f * x);
    return (1.0f - e) / (1.0f + e);
}
__device__ __forceinline__ unsigned ld_acq_gpu(const unsigned* p) {
    unsigned v;
    asm volatile("ld.acquire.gpu.u32 %0, [%1];" : "=r"(v) : "l"(p));
    return v;
}
__device__ __forceinline__ uint32_t smem_u32(const void* p) {
    uint32_t a;
    asm("{ .reg .u64 t; cvta.to.shared.u64 t, %1; cvt.u32.u64 %0, t; }"
        : "=r"(a) : "l"(p));
    return a;
}

__global__ void lstm_init_kernel() {
    if (threadIdx.x == 0) g_cnt = 0u;
}

__global__ void __launch_bounds__(TPB) lstm_kernel(
    const float* __restrict__ x,      // [1024]
    const float* __restrict__ W_ih,   // [4096,1024] row-major
    const float* __restrict__ W_hh,   // [4096,1024] row-major
    const float* __restrict__ b_ih,   // [4096]
    const float* __restrict__ b_hh,   // [4096]
    float* __restrict__ out,          // [N,1024]
    int N)
{
    __shared__ float    sh_h[HDIM];        // warp w owns [64w,64w+64): private
    __shared__ float    sh_part[2][TPB];   // parity-double-buffered partials
    __shared__ unsigned sh_step;           // monotonic step relay

    const int tid = threadIdx.x;
    const int w   = tid >> 5;
    const int l   = tid & 31;
    const int cta = blockIdx.x;
    const int gt  = l >> 3;                // gate 0..3 (i,f,g,o)  [warp0 tail]
    const int jj  = l & 7;                 // local h index 0..7
    const int rowG = gt * HDIM + cta * 8 + jj;
    const uint32_t stepAddr = smem_u32(&sh_step);

    if (tid == 0) sh_step = 0u;

    // ---- stage x into shared (reuse sh_h) ----
    ((float2*)sh_h)[tid] = ((const float2*)x)[tid];   // 512 * 2 = 1024 floats
    __syncthreads();

    // ---- prologue: x_gates = x @ W_ih^T + b_ih + b_hh for this CTA's rows ----
    float xg = 0.f;
    {
        const ull* wp = (const ull*)W_ih + (size_t)rowG * (HDIM / 2) + w * WPT;
        const ull* hp = (const ull*)sh_h + w * WPT;
        ull a0 = 0, a1 = 0, a2 = 0, a3 = 0;
        #pragma unroll
        for (int i = 0; i < WPT; i += 4) {
            a0 = ffma2(wp[i + 0], hp[i + 0], a0);
            a1 = ffma2(wp[i + 1], hp[i + 1], a1);
            a2 = ffma2(wp[i + 2], hp[i + 2], a2);
            a3 = ffma2(wp[i + 3], hp[i + 3], a3);
        }
        a0 = fadd2(a0, a1); a2 = fadd2(a2, a3); a0 = fadd2(a0, a2);
        sh_part[0][w * 32 + l] = pairsum(a0);
        __syncthreads();
        if (w == 0) {
            float s = 0.f;
            #pragma unroll
            for (int ww = 0; ww < NWARP; ww++) s += sh_part[0][ww * 32 + l];
            xg = s + b_ih[rowG] + b_hh[rowG];
        }
        __syncthreads();
    }

    // ---- preload W_hh slice into registers (32 f32x2 pairs / thread) ----
    ull wreg[WPT];
    {
        const ull* wp = (const ull*)W_hh + (size_t)rowG * (HDIM / 2) + w * WPT;
        #pragma unroll
        for (int i = 0; i < WPT; i++) wreg[i] = wp[i];
    }

    // ---- recurrence: ONE __syncthreads per step ----
    float c = 0.f;
    unsigned target = 0u;                  // = 128*t

    for (int t = 0; t < N; ++t) {
        float dot = 0.f;
        if (t > 0) {
            const int p = (t - 1) & 1;
            const unsigned tt = (unsigned)t;

            if (w == 0) {
                if (l == 0) {
                    // single poller per CTA on the aggregate counter
                    while ((int)(ld_acq_gpu(&g_cnt) - target) < 0) { }
                    asm volatile("st.release.cta.shared.u32 [%0], %1;"
                                 :: "r"(stepAddr), "r"(tt) : "memory");
                }
                __syncwarp();
            } else {
                // local smem spin: zero L2 traffic
                unsigned v;
                do {
                    asm volatile("ld.acquire.cta.shared.u32 %0, [%1];"
                                 : "=r"(v) : "r"(stepAddr) : "memory");
                } while ((int)(v - tt) < 0);
            }

            // stage this warp's 64-float k-slice into its private smem region
            float2 hv = __ldcg((const float2*)(g_hbuf[p] + w * 64) + l);
            *((float2*)(sh_h + w * 64) + l) = hv;
            __syncwarp();

            const ull* hp = (const ull*)(sh_h + w * 64);
            ull c0 = 0, c1 = 0, c2 = 0, c3 = 0;
            #pragma unroll
            for (int i = 0; i < WPT; i += 4) {
                c0 = ffma2(wreg[i + 0], hp[i + 0], c0);
                c1 = ffma2(wreg[i + 1], hp[i + 1], c1);
                c2 = ffma2(wreg[i + 2], hp[i + 2], c2);
                c3 = ffma2(wreg[i + 3], hp[i + 3], c3);
            }
            c0 = fadd2(c0, c1); c2 = fadd2(c2, c3); c0 = fadd2(c0, c2);
            dot = pairsum(c0);
        }
        sh_part[t & 1][w * 32 + l] = dot;
        __syncthreads();

        if (w == 0) {
            float s = 0.f;
            #pragma unroll
            for (int ww = 0; ww < NWARP; ww++) s += sh_part[t & 1][ww * 32 + l];
            // activation on ALL 32 lanes (parallel), then gather via shfl
            float val = xg + s;
            float act = (gt == 2) ? tanh_fast(val) : sigf(val);
            float a_f = __shfl_sync(0xffffffffu, act, l + 8);
            float a_g = __shfl_sync(0xffffffffu, act, l + 16);
            float a_o = __shfl_sync(0xffffffffu, act, l + 24);
            float hn = 0.f;
            if (l < 8) {
                c  = a_f * c + act * a_g;       // act=i, a_f=f, a_g=g
                hn = a_o * tanh_fast(c);
                __stcg(&g_hbuf[t & 1][cta * 8 + l], hn);
            }
            __syncwarp();
            if (l == 0) {
                __threadfence();
                asm volatile("red.global.gpu.add.u32 [%0], %1;"
                             :: "l"(&g_cnt), "r"(1u) : "memory");
            }
            // out store AFTER release: fence never drains the DRAM write
            if (l < 8)
                __stcs(out + (size_t)t * HDIM + cta * 8 + l, hn);
        }
        target += NCTA;
        // no trailing barrier: sh_part for step t+1 has opposite parity; the
        // global counter requires ALL CTAs, bounding cross-CTA skew to 1 step.
    }
}

extern "C" void kernel_launch(void* const* d_in, const int* in_sizes, int n_in,
                              void* d_out, int out_size) {
    const float* x    = (const float*)d_in[0];
    const float* W_ih = (const float*)d_in[1];
    const float* W_hh = (const float*)d_in[2];
    const float* b_ih = (const float*)d_in[3];
    const float* b_hh = (const float*)d_in[4];
    float* out = (float*)d_out;
    const int N = out_size / HDIM;

    lstm_init_kernel<<<1, 32>>>();
    lstm_kernel<<<NCTA, TPB>>>(x, W_ih, W_hh, b_ih, b_hh, out, N);
}